// round 1
// baseline (speedup 1.0000x reference)
#include <cuda_runtime.h>
#include <math.h>

// Problem constants (validated at runtime against in_sizes)
#define MAXN 50000
#define MAXE 800000
#define DIN 64      // DIN_N == DIN_E == 64
#define DOUT 128    // H*DOUT = 4*32
#define KDIM 192    // 2*DIN_N + DIN_E

// Scratch (device globals — no allocation allowed)
__device__ float g_ht[MAXN * DOUT];      // transformed node feats [N,128]
__device__ float g_a[MAXE * 4];          // attention logits, then exp values [E,4]
__device__ float g_amax[MAXN * 4];       // per-(dst,head) max
__device__ float g_denom[MAXN * 4];      // per-(dst,head) softmax denom

__device__ __forceinline__ void atomicMaxFloat(float* addr, float value) {
    if (value >= 0.0f) atomicMax((int*)addr, __float_as_int(value));
    else               atomicMin((unsigned int*)addr, __float_as_uint(value));
}

// ---------------------------------------------------------------------------
// Kernel 0: init h_out region to 0, amax to -inf, denom to 0
// ---------------------------------------------------------------------------
__global__ void init_kernel(float* h_out, int N) {
    int stride = gridDim.x * blockDim.x;
    int total_h = N * DOUT;
    for (int i = blockIdx.x * blockDim.x + threadIdx.x; i < total_h; i += stride)
        h_out[i] = 0.0f;
    int total_a = N * 4;
    for (int i = blockIdx.x * blockDim.x + threadIdx.x; i < total_a; i += stride) {
        g_amax[i] = -INFINITY;
        g_denom[i] = 0.0f;
    }
}

// ---------------------------------------------------------------------------
// Kernel 1: node transform  g_ht = nfeats @ W_nodes + b_nodes   [N,128]
// block = 128 threads, each thread owns one output column
// ---------------------------------------------------------------------------
__global__ void node_kernel(const float* __restrict__ nfeats,
                            const float* __restrict__ W_nodes,
                            const float* __restrict__ b_nodes,
                            int N) {
    __shared__ float Ws[DIN * DOUT];   // 32 KB
    __shared__ float xs[DIN];
    int tid = threadIdx.x;

    for (int i = tid; i < DIN * DOUT / 4; i += 128)
        ((float4*)Ws)[i] = ((const float4*)W_nodes)[i];
    float b = b_nodes[tid];
    __syncthreads();

    for (int n = blockIdx.x; n < N; n += gridDim.x) {
        if (tid < DIN / 4)
            ((float4*)xs)[tid] = ((const float4*)(nfeats + (size_t)n * DIN))[tid];
        __syncthreads();
        float acc = b;
#pragma unroll
        for (int k = 0; k < DIN; k++)
            acc += xs[k] * Ws[k * DOUT + tid];
        g_ht[(size_t)n * DOUT + tid] = acc;
        __syncthreads();
    }
}

// ---------------------------------------------------------------------------
// Kernel 2: edge GEMM + leaky_relu + attention logits + segment max
// 64-edge x 128-col tile per block; 512 threads; 4x4 register tile/thread.
// W_edges (192x128 = 98KB) resident in smem.
// ---------------------------------------------------------------------------
#define TE 64
__global__ __launch_bounds__(512, 1)
void edge_kernel(const float* __restrict__ nfeats,
                 const float* __restrict__ efeats,
                 const int* __restrict__ src,
                 const int* __restrict__ dst,
                 const float* __restrict__ W_edges,
                 const float* __restrict__ b_edges,
                 const float* __restrict__ W_attn,
                 float* __restrict__ f_out,
                 int E) {
    extern __shared__ float sm[];
    float* Ws  = sm;                      // 192*128
    float* Ss  = Ws + KDIM * DOUT;        // 64*192
    float* bs  = Ss + TE * KDIM;          // 128
    float* was = bs + DOUT;               // 32
    int*  sidx = (int*)(was + 32);        // 64
    int*  didx = sidx + TE;               // 64

    int tid = threadIdx.x;

    for (int i = tid; i < KDIM * DOUT / 4; i += 512)
        ((float4*)Ws)[i] = ((const float4*)W_edges)[i];
    if (tid < DOUT) bs[tid] = b_edges[tid];
    if (tid < 32)
        was[tid] = W_attn[tid * 4] + W_attn[tid * 4 + 1] +
                   W_attn[tid * 4 + 2] + W_attn[tid * 4 + 3];

    int e0 = blockIdx.x * TE;
    if (tid < TE) {
        int e = e0 + tid;
        sidx[tid] = (e < E) ? src[e] : 0;
        didx[tid] = (e < E) ? dst[e] : 0;
    }
    __syncthreads();

    // gather stack rows: [nfeats[src] | efeats | nfeats[dst]] as 48 float4 each
    for (int i = tid; i < TE * 48; i += 512) {
        int le  = i / 48;
        int seg = i % 48;
        int e   = e0 + le;
        float4 v;
        if (seg < 16)
            v = ((const float4*)(nfeats + (size_t)sidx[le] * DIN))[seg];
        else if (seg < 32)
            v = (e < E) ? ((const float4*)(efeats + (size_t)e * DIN))[seg - 16]
                        : make_float4(0, 0, 0, 0);
        else
            v = ((const float4*)(nfeats + (size_t)didx[le] * DIN))[seg - 32];
        ((float4*)(Ss + le * KDIM))[seg] = v;
    }
    __syncthreads();

    int cg = tid & 31;        // column group (lane): cols c0..c0+3
    int eg = tid >> 5;        // edge group (warp): edges le0..le0+3
    int c0 = cg * 4;
    int le0 = eg * 4;

    float acc[4][4];
#pragma unroll
    for (int i = 0; i < 4; i++)
#pragma unroll
        for (int j = 0; j < 4; j++)
            acc[i][j] = bs[c0 + j];

    const float* Sp = Ss + le0 * KDIM;
#pragma unroll 4
    for (int k = 0; k < KDIM; k++) {
        float4 w = *reinterpret_cast<const float4*>(Ws + k * DOUT + c0);
        float s0 = Sp[k];
        float s1 = Sp[KDIM + k];
        float s2 = Sp[2 * KDIM + k];
        float s3 = Sp[3 * KDIM + k];
        acc[0][0] += s0 * w.x; acc[0][1] += s0 * w.y; acc[0][2] += s0 * w.z; acc[0][3] += s0 * w.w;
        acc[1][0] += s1 * w.x; acc[1][1] += s1 * w.y; acc[1][2] += s1 * w.z; acc[1][3] += s1 * w.w;
        acc[2][0] += s2 * w.x; acc[2][1] += s2 * w.y; acc[2][2] += s2 * w.z; acc[2][3] += s2 * w.w;
        acc[3][0] += s3 * w.x; acc[3][1] += s3 * w.y; acc[3][2] += s3 * w.z; acc[3][3] += s3 * w.w;
    }

    // epilogue: leaky relu, write f_out, reduce attention logit per (edge, head)
    int h = c0 >> 5;                 // head = c0/32 (same for all 4 cols)
    float wa0 = was[(c0 & 31) + 0];
    float wa1 = was[(c0 & 31) + 1];
    float wa2 = was[(c0 & 31) + 2];
    float wa3 = was[(c0 & 31) + 3];

#pragma unroll
    for (int i = 0; i < 4; i++) {
        float4 fv;
        fv.x = acc[i][0] >= 0.f ? acc[i][0] : 0.01f * acc[i][0];
        fv.y = acc[i][1] >= 0.f ? acc[i][1] : 0.01f * acc[i][1];
        fv.z = acc[i][2] >= 0.f ? acc[i][2] : 0.01f * acc[i][2];
        fv.w = acc[i][3] >= 0.f ? acc[i][3] : 0.01f * acc[i][3];
        int e = e0 + le0 + i;
        if (e < E)
            *reinterpret_cast<float4*>(f_out + (size_t)e * DOUT + c0) = fv;

        float part = fv.x * wa0 + fv.y * wa1 + fv.z * wa2 + fv.w * wa3;
        // reduce across the 8 lanes that share this head (lanes 8h..8h+7)
        part += __shfl_xor_sync(0xffffffffu, part, 4);
        part += __shfl_xor_sync(0xffffffffu, part, 2);
        part += __shfl_xor_sync(0xffffffffu, part, 1);
        if ((cg & 7) == 0 && e < E) {
            g_a[(size_t)e * 4 + h] = part;
            atomicMaxFloat(&g_amax[(size_t)didx[le0 + i] * 4 + h], part);
        }
    }
}

// ---------------------------------------------------------------------------
// Kernel 3: exp(a - amax[dst]) and segment-sum denom
// ---------------------------------------------------------------------------
__global__ void softmax_kernel(const int* __restrict__ dst, int E) {
    int stride = gridDim.x * blockDim.x;
    int total = E * 4;
    for (int i = blockIdx.x * blockDim.x + threadIdx.x; i < total; i += stride) {
        int e = i >> 2;
        int h = i & 3;
        int d = dst[e];
        float v = expf(g_a[i] - g_amax[d * 4 + h]);
        g_a[i] = v;
        atomicAdd(&g_denom[d * 4 + h], v);
    }
}

// ---------------------------------------------------------------------------
// Kernel 4: weighted scatter  h_out[dst] += alpha * h_t[src]
// one warp per edge, float4 atomics
// ---------------------------------------------------------------------------
__global__ void scatter_kernel(const int* __restrict__ src,
                               const int* __restrict__ dst,
                               float* __restrict__ h_out,
                               int E) {
    int gwarp = (blockIdx.x * blockDim.x + threadIdx.x) >> 5;
    int lane  = threadIdx.x & 31;
    if (gwarp >= E) return;
    int s = src[gwarp];
    int d = dst[gwarp];
    int h = lane >> 3;                       // cols lane*4 .. lane*4+3, head = (lane*4)/32
    float alpha = g_a[(size_t)gwarp * 4 + h] / g_denom[(size_t)d * 4 + h];
    float4 ht = *reinterpret_cast<const float4*>(g_ht + (size_t)s * DOUT + lane * 4);
    float4 v = make_float4(alpha * ht.x, alpha * ht.y, alpha * ht.z, alpha * ht.w);
    atomicAdd(reinterpret_cast<float4*>(h_out + (size_t)d * DOUT + lane * 4), v);
}

// ---------------------------------------------------------------------------
extern "C" void kernel_launch(void* const* d_in, const int* in_sizes, int n_in,
                              void* d_out, int out_size) {
    const float* nfeats  = (const float*)d_in[0];
    const float* efeats  = (const float*)d_in[1];
    const int*   src     = (const int*)d_in[2];
    const int*   dst     = (const int*)d_in[3];
    const float* W_nodes = (const float*)d_in[4];
    const float* b_nodes = (const float*)d_in[5];
    const float* W_edges = (const float*)d_in[6];
    const float* b_edges = (const float*)d_in[7];
    const float* W_attn  = (const float*)d_in[8];

    int N = in_sizes[0] / DIN;
    int E = in_sizes[2];

    float* h_out = (float*)d_out;                      // [N, 4, 32]
    float* f_out = (float*)d_out + (size_t)N * DOUT;   // [E, 4, 32]

    // allow >48KB dynamic smem for the edge GEMM
    size_t edge_smem = (size_t)(KDIM * DOUT + TE * KDIM + DOUT + 32) * sizeof(float)
                     + 2 * TE * sizeof(int);
    cudaFuncSetAttribute(edge_kernel, cudaFuncAttributeMaxDynamicSharedMemorySize,
                         (int)edge_smem);

    init_kernel<<<512, 256>>>(h_out, N);
    node_kernel<<<1024, 128>>>(nfeats, W_nodes, b_nodes, N);
    int eblocks = (E + TE - 1) / TE;
    edge_kernel<<<eblocks, 512, edge_smem>>>(nfeats, efeats, src, dst,
                                             W_edges, b_edges, W_attn, f_out, E);
    softmax_kernel<<<1024, 256>>>(dst, E);
    scatter_kernel<<<(E * 32 + 255) / 256, 256>>>(src, dst, h_out, E);
}

// round 2
// speedup vs baseline: 1.3677x; 1.3677x over previous
#include <cuda_runtime.h>
#include <math.h>

#define MAXN 50000
#define MAXE 800000
#define DIN 64      // DIN_N == DIN_E == 64
#define DOUT 128    // H*DOUT = 4*32
#define KDIM 192    // 2*DIN_N + DIN_E
#define TE 128      // edges per block tile

// Scratch (device globals — no allocation allowed)
__device__ float g_ht[MAXN * DOUT];      // transformed node feats [N,128]
__device__ float g_a[MAXE * 4];          // attention logits, then exp values [E,4]
__device__ float g_amax[MAXN * 4];       // per-(dst,head) max
__device__ float g_denom[MAXN * 4];      // per-(dst,head) softmax denom

__device__ __forceinline__ void atomicMaxFloat(float* addr, float value) {
    if (value >= 0.0f) atomicMax((int*)addr, __float_as_int(value));
    else               atomicMin((unsigned int*)addr, __float_as_uint(value));
}

__device__ __forceinline__ unsigned long long pack2(float lo, float hi) {
    unsigned long long r;
    asm("mov.b64 %0, {%1, %2};" : "=l"(r) : "f"(lo), "f"(hi));
    return r;
}
__device__ __forceinline__ void unpack2(unsigned long long v, float& lo, float& hi) {
    asm("mov.b64 {%0, %1}, %2;" : "=f"(lo), "=f"(hi) : "l"(v));
}
__device__ __forceinline__ void fma2(unsigned long long& d, unsigned long long a,
                                     unsigned long long b) {
    asm("fma.rn.f32x2 %0, %1, %2, %0;" : "+l"(d) : "l"(a), "l"(b));
}

// ---------------------------------------------------------------------------
// Kernel 0: init h_out to 0, amax to -inf, denom to 0
// ---------------------------------------------------------------------------
__global__ void init_kernel(float* h_out, int N) {
    int stride = gridDim.x * blockDim.x;
    int total_h = N * DOUT;
    for (int i = blockIdx.x * blockDim.x + threadIdx.x; i < total_h; i += stride)
        h_out[i] = 0.0f;
    int total_a = N * 4;
    for (int i = blockIdx.x * blockDim.x + threadIdx.x; i < total_a; i += stride) {
        g_amax[i] = -INFINITY;
        g_denom[i] = 0.0f;
    }
}

// ---------------------------------------------------------------------------
// Kernel 1: node transform  g_ht = nfeats @ W_nodes + b_nodes   [N,128]
// ---------------------------------------------------------------------------
__global__ void node_kernel(const float* __restrict__ nfeats,
                            const float* __restrict__ W_nodes,
                            const float* __restrict__ b_nodes,
                            int N) {
    __shared__ float Ws[DIN * DOUT];   // 32 KB
    __shared__ float xs[DIN];
    int tid = threadIdx.x;

    for (int i = tid; i < DIN * DOUT / 4; i += 128)
        ((float4*)Ws)[i] = ((const float4*)W_nodes)[i];
    float b = b_nodes[tid];
    __syncthreads();

    for (int n = blockIdx.x; n < N; n += gridDim.x) {
        if (tid < DIN / 4)
            ((float4*)xs)[tid] = ((const float4*)(nfeats + (size_t)n * DIN))[tid];
        __syncthreads();
        float acc = b;
#pragma unroll
        for (int k = 0; k < DIN; k++)
            acc += xs[k] * Ws[k * DOUT + tid];
        g_ht[(size_t)n * DOUT + tid] = acc;
        __syncthreads();
    }
}

// ---------------------------------------------------------------------------
// Kernel 2: edge GEMM (f32x2 packed) + leaky_relu + attention + segment max
// 128-edge x 128-col tile per block; 512 threads.
// Each thread: 8 edges (as 4 f32x2 pairs) x 4 cols.
// Smem: W_edges [192][128] + transposed stack St [k][edge].
// ---------------------------------------------------------------------------
__global__ __launch_bounds__(512, 1)
void edge_kernel(const float* __restrict__ nfeats,
                 const float* __restrict__ efeats,
                 const int* __restrict__ src,
                 const int* __restrict__ dst,
                 const float* __restrict__ W_edges,
                 const float* __restrict__ b_edges,
                 const float* __restrict__ W_attn,
                 float* __restrict__ f_out,
                 int E) {
    extern __shared__ float sm[];
    float* Ws  = sm;                      // 192*128
    float* St  = Ws + KDIM * DOUT;        // 192*128  (transposed: [k][edge])
    float* bs  = St + KDIM * TE;          // 128
    float* was = bs + DOUT;               // 32
    int*  sidx = (int*)(was + 32);        // 128
    int*  didx = sidx + TE;               // 128

    int tid  = threadIdx.x;
    int lane = tid & 31;
    int warp = tid >> 5;

    for (int i = tid; i < KDIM * DOUT / 4; i += 512)
        ((float4*)Ws)[i] = ((const float4*)W_edges)[i];
    if (tid < DOUT) bs[tid] = b_edges[tid];
    if (tid < 32)
        was[tid] = W_attn[tid * 4] + W_attn[tid * 4 + 1] +
                   W_attn[tid * 4 + 2] + W_attn[tid * 4 + 3];

    int e0 = blockIdx.x * TE;
    if (tid < TE) {
        int e = e0 + tid;
        sidx[tid] = (e < E) ? src[e] : 0;
        didx[tid] = (e < E) ? dst[e] : 0;
    }
    __syncthreads();

    // gather stack rows into TRANSPOSED smem: St[k][le]
    // 48 float4-segments per edge x 4 groups of 32 edges = 192 warp-tasks
    for (int t = warp; t < 192; t += 16) {
        int seg = t >> 2;           // 0..47 (which float4 of the 192-row)
        int eg  = t & 3;            // edge group
        int le  = eg * 32 + lane;
        int e   = e0 + le;
        float4 v;
        if (seg < 16)
            v = ((const float4*)(nfeats + (size_t)sidx[le] * DIN))[seg];
        else if (seg < 32)
            v = (e < E) ? ((const float4*)(efeats + (size_t)e * DIN))[seg - 16]
                        : make_float4(0, 0, 0, 0);
        else
            v = ((const float4*)(nfeats + (size_t)didx[le] * DIN))[seg - 32];
        int k0 = seg * 4;
        St[(k0 + 0) * TE + le] = v.x;
        St[(k0 + 1) * TE + le] = v.y;
        St[(k0 + 2) * TE + le] = v.z;
        St[(k0 + 3) * TE + le] = v.w;
    }
    __syncthreads();

    int c0  = lane * 4;   // this thread's 4 output columns
    int le0 = warp * 8;   // this thread's 8 edges

    // acc[p][c]: edge pair (le0+2p, le0+2p+1), column c0+c
    unsigned long long acc[4][4];
#pragma unroll
    for (int p = 0; p < 4; p++)
#pragma unroll
        for (int c = 0; c < 4; c++)
            acc[p][c] = pack2(bs[c0 + c], bs[c0 + c]);

#pragma unroll 2
    for (int k = 0; k < KDIM; k++) {
        float4 w = *reinterpret_cast<const float4*>(Ws + k * DOUT + c0);
        unsigned long long wd[4];
        wd[0] = pack2(w.x, w.x);
        wd[1] = pack2(w.y, w.y);
        wd[2] = pack2(w.z, w.z);
        wd[3] = pack2(w.w, w.w);
        ulonglong2 sA = *reinterpret_cast<const ulonglong2*>(St + k * TE + le0);
        ulonglong2 sB = *reinterpret_cast<const ulonglong2*>(St + k * TE + le0 + 4);
        unsigned long long sp[4] = {sA.x, sA.y, sB.x, sB.y};
#pragma unroll
        for (int p = 0; p < 4; p++) {
#pragma unroll
            for (int c = 0; c < 4; c++)
                fma2(acc[p][c], sp[p], wd[c]);
        }
    }

    // epilogue: leaky relu, f_out store, attention logit reduce + segment max
    int h = lane >> 3;
    float wa0 = was[(lane & 7) * 4 + 0];
    float wa1 = was[(lane & 7) * 4 + 1];
    float wa2 = was[(lane & 7) * 4 + 2];
    float wa3 = was[(lane & 7) * 4 + 3];

#pragma unroll
    for (int p = 0; p < 4; p++) {
        float lo[4], hi[4];
#pragma unroll
        for (int c = 0; c < 4; c++) unpack2(acc[p][c], lo[c], hi[c]);
#pragma unroll
        for (int half = 0; half < 2; half++) {
            float* f = half ? hi : lo;
            float4 fv;
            fv.x = f[0] >= 0.f ? f[0] : 0.01f * f[0];
            fv.y = f[1] >= 0.f ? f[1] : 0.01f * f[1];
            fv.z = f[2] >= 0.f ? f[2] : 0.01f * f[2];
            fv.w = f[3] >= 0.f ? f[3] : 0.01f * f[3];
            int le = le0 + 2 * p + half;
            int e  = e0 + le;
            if (e < E)
                *reinterpret_cast<float4*>(f_out + (size_t)e * DOUT + c0) = fv;

            float part = fv.x * wa0 + fv.y * wa1 + fv.z * wa2 + fv.w * wa3;
            part += __shfl_xor_sync(0xffffffffu, part, 4);
            part += __shfl_xor_sync(0xffffffffu, part, 2);
            part += __shfl_xor_sync(0xffffffffu, part, 1);
            if ((lane & 7) == 0 && e < E) {
                g_a[(size_t)e * 4 + h] = part;
                atomicMaxFloat(&g_amax[(size_t)didx[le] * 4 + h], part);
            }
        }
    }
}

// ---------------------------------------------------------------------------
// Kernel 3: exp(a - amax[dst]) and segment-sum denom
// ---------------------------------------------------------------------------
__global__ void softmax_kernel(const int* __restrict__ dst, int E) {
    int stride = gridDim.x * blockDim.x;
    int total = E * 4;
    for (int i = blockIdx.x * blockDim.x + threadIdx.x; i < total; i += stride) {
        int e = i >> 2;
        int h = i & 3;
        int d = dst[e];
        float v = expf(g_a[i] - g_amax[d * 4 + h]);
        g_a[i] = v;
        atomicAdd(&g_denom[d * 4 + h], v);
    }
}

// ---------------------------------------------------------------------------
// Kernel 4: weighted scatter  h_out[dst] += alpha * h_t[src]
// ---------------------------------------------------------------------------
__global__ void scatter_kernel(const int* __restrict__ src,
                               const int* __restrict__ dst,
                               float* __restrict__ h_out,
                               int E) {
    int gwarp = (blockIdx.x * blockDim.x + threadIdx.x) >> 5;
    int lane  = threadIdx.x & 31;
    if (gwarp >= E) return;
    int s = src[gwarp];
    int d = dst[gwarp];
    int h = lane >> 3;
    float alpha = g_a[(size_t)gwarp * 4 + h] / g_denom[(size_t)d * 4 + h];
    float4 ht = *reinterpret_cast<const float4*>(g_ht + (size_t)s * DOUT + lane * 4);
    float4 v = make_float4(alpha * ht.x, alpha * ht.y, alpha * ht.z, alpha * ht.w);
    atomicAdd(reinterpret_cast<float4*>(h_out + (size_t)d * DOUT + lane * 4), v);
}

// ---------------------------------------------------------------------------
extern "C" void kernel_launch(void* const* d_in, const int* in_sizes, int n_in,
                              void* d_out, int out_size) {
    const float* nfeats  = (const float*)d_in[0];
    const float* efeats  = (const float*)d_in[1];
    const int*   src     = (const int*)d_in[2];
    const int*   dst     = (const int*)d_in[3];
    const float* W_nodes = (const float*)d_in[4];
    const float* b_nodes = (const float*)d_in[5];
    const float* W_edges = (const float*)d_in[6];
    const float* b_edges = (const float*)d_in[7];
    const float* W_attn  = (const float*)d_in[8];

    int N = in_sizes[0] / DIN;
    int E = in_sizes[2];

    float* h_out = (float*)d_out;                      // [N, 4, 32]
    float* f_out = (float*)d_out + (size_t)N * DOUT;   // [E, 4, 32]

    size_t edge_smem = (size_t)(KDIM * DOUT + KDIM * TE + DOUT + 32) * sizeof(float)
                     + 2 * TE * sizeof(int);
    cudaFuncSetAttribute(edge_kernel, cudaFuncAttributeMaxDynamicSharedMemorySize,
                         (int)edge_smem);

    init_kernel<<<512, 256>>>(h_out, N);
    node_kernel<<<1024, 128>>>(nfeats, W_nodes, b_nodes, N);
    int eblocks = (E + TE - 1) / TE;
    edge_kernel<<<eblocks, 512, edge_smem>>>(nfeats, efeats, src, dst,
                                             W_edges, b_edges, W_attn, f_out, E);
    softmax_kernel<<<1024, 256>>>(dst, E);
    scatter_kernel<<<(E * 32 + 255) / 256, 256>>>(src, dst, h_out, E);
}